// round 1
// baseline (speedup 1.0000x reference)
#include <cuda_runtime.h>
#include <cuda_bf16.h>

// Scratch for block partials (no cudaMalloc allowed).
#define MAX_BLOCKS 4096
__device__ float g_partials[MAX_BLOCKS];

// ---- polynomial helpers (restricted domains, fp32, FMA pipe only) ----

// sin(x), x in [0, ~0.54]  (Taylor deg 7, abs err < 1e-8)
__device__ __forceinline__ float sin_poly(float x) {
    float x2 = x * x;
    float p = fmaf(x2, fmaf(x2, fmaf(x2, -1.9841270e-4f, 8.3333333e-3f),
                            -1.6666667e-1f), 1.0f);
    return x * p;
}

// asin(x), x in [0, ~0.27]  (Taylor deg 7, rel err < 1e-6)
__device__ __forceinline__ float asin_poly(float x) {
    float x2 = x * x;
    float p = fmaf(x2, fmaf(x2, fmaf(x2, 4.4642857e-2f, 7.5000000e-2f),
                            1.6666667e-1f), 1.0f);
    return x * p;
}

// cos(x), |x| <= pi/2  (Taylor deg 10, abs err < 5e-7)
__device__ __forceinline__ float cos_poly(float x) {
    float x2 = x * x;
    return fmaf(x2, fmaf(x2, fmaf(x2, fmaf(x2, fmaf(x2, -2.7557319e-7f,
                 2.4801587e-5f), -1.3888889e-3f), 4.1666667e-2f), -0.5f), 1.0f);
}

// loss for one box pair = 1 - sph_iou
// area(a,b) = 4*acos(-sin(a/2)sin(b/2)) - 2pi == 4*asin(sin(a/2)sin(b/2))
__device__ __forceinline__ float box_loss(float t1, float p1, float a1, float b1,
                                          float t2, float p2, float a2, float b2) {
    float ha1 = 0.5f * a1, hb1 = 0.5f * b1;
    float ha2 = 0.5f * a2, hb2 = 0.5f * b2;

    float area1 = 4.0f * asin_poly(sin_poly(ha1) * sin_poly(hb1));
    float area2 = 4.0f * asin_poly(sin_poly(ha2) * sin_poly(hb2));

    float c   = cos_poly(0.5f * (p1 + p2));
    float dfx = (t2 - t1) * c;
    float dfy = p2 - p1;

    float iw = fminf(ha1, dfx + ha2) - fmaxf(-ha1, dfx - ha2);
    iw = fmaxf(iw, 0.0f);
    float ih = fminf(hb1, dfy + hb2) - fmaxf(-hb1, dfy - hb2);
    ih = fmaxf(ih, 0.0f);

    float inter = 4.0f * asin_poly(sin_poly(0.5f * iw) * sin_poly(0.5f * ih));
    float uni   = fmaxf(area1 + area2 - inter, 1e-8f);
    return 1.0f - __fdividef(inter, uni);
}

// Main kernel: each "job" = 4 consecutive boxes = 5 aligned float4 per tensor.
__global__ void __launch_bounds__(256)
sph_iou_loss_kernel(const float4* __restrict__ pr4, const float4* __restrict__ tg4,
                    int jobs) {
    float acc = 0.0f;
    for (int j = blockIdx.x * blockDim.x + threadIdx.x; j < jobs;
         j += gridDim.x * blockDim.x) {
        int base = 5 * j;
        float4 p0 = pr4[base + 0], p1 = pr4[base + 1], p2 = pr4[base + 2],
               p3 = pr4[base + 3], p4 = pr4[base + 4];
        float4 q0 = tg4[base + 0], q1 = tg4[base + 1], q2 = tg4[base + 2],
               q3 = tg4[base + 3], q4 = tg4[base + 4];

        // box k fields (theta,phi,fov_x,fov_y) at flat float offsets 5k..5k+3
        acc += box_loss(p0.x, p0.y, p0.z, p0.w,  q0.x, q0.y, q0.z, q0.w);
        acc += box_loss(p1.y, p1.z, p1.w, p2.x,  q1.y, q1.z, q1.w, q2.x);
        acc += box_loss(p2.z, p2.w, p3.x, p3.y,  q2.z, q2.w, q3.x, q3.y);
        acc += box_loss(p3.w, p4.x, p4.y, p4.z,  q3.w, q4.x, q4.y, q4.z);
    }

    // warp reduce
    #pragma unroll
    for (int o = 16; o > 0; o >>= 1)
        acc += __shfl_down_sync(0xFFFFFFFFu, acc, o);

    __shared__ float sm[8];
    int lane = threadIdx.x & 31;
    int wid  = threadIdx.x >> 5;
    if (lane == 0) sm[wid] = acc;
    __syncthreads();
    if (wid == 0) {
        float v = (lane < (blockDim.x >> 5)) ? sm[lane] : 0.0f;
        #pragma unroll
        for (int o = 4; o > 0; o >>= 1)
            v += __shfl_down_sync(0xFFFFFFFFu, v, o);
        if (lane == 0) g_partials[blockIdx.x] = v;
    }
}

// Final reduction: sum block partials in double, handle tail boxes, write mean.
__global__ void __launch_bounds__(256)
sph_iou_reduce_kernel(const float* __restrict__ pr, const float* __restrict__ tg,
                      int n, int nblocks, float* __restrict__ out) {
    __shared__ double sm[256];
    double s = 0.0;
    for (int i = threadIdx.x; i < nblocks; i += blockDim.x)
        s += (double)g_partials[i];

    if (threadIdx.x == 0) {
        int tail = n & 3;
        int base = n - tail;
        for (int k = 0; k < tail; ++k) {
            const float* P = pr + (size_t)(base + k) * 5;
            const float* T = tg + (size_t)(base + k) * 5;
            s += (double)box_loss(P[0], P[1], P[2], P[3], T[0], T[1], T[2], T[3]);
        }
    }

    sm[threadIdx.x] = s;
    __syncthreads();
    for (int stride = 128; stride > 0; stride >>= 1) {
        if (threadIdx.x < stride) sm[threadIdx.x] += sm[threadIdx.x + stride];
        __syncthreads();
    }
    if (threadIdx.x == 0) out[0] = (float)(sm[0] / (double)n);
}

extern "C" void kernel_launch(void* const* d_in, const int* in_sizes, int n_in,
                              void* d_out, int out_size) {
    const float* preds   = (const float*)d_in[0];
    const float* targets = (const float*)d_in[1];
    float* out = (float*)d_out;

    int n    = in_sizes[0] / 5;       // number of boxes
    int jobs = n >> 2;                // 4 boxes per thread-job

    int threads = 256;
    int blocks  = (jobs + threads - 1) / threads;
    if (blocks > MAX_BLOCKS) blocks = MAX_BLOCKS;
    if (blocks < 1) blocks = 1;

    sph_iou_loss_kernel<<<blocks, threads>>>(
        (const float4*)preds, (const float4*)targets, jobs);
    sph_iou_reduce_kernel<<<1, 256>>>(preds, targets, n, blocks, out);
}

// round 4
// speedup vs baseline: 1.0667x; 1.0667x over previous
#include <cuda_runtime.h>
#include <cuda_bf16.h>

#define MAX_BLOCKS 2048
__device__ float g_partials[MAX_BLOCKS];
__device__ unsigned int g_done = 0;   // self-resets via atomicInc wraparound

// ---- polynomial helpers (restricted domains, fp32, FMA pipe only) ----

// sin(x), x in [0, ~0.54]  (Taylor deg 7, abs err < 1e-8)
__device__ __forceinline__ float sin_poly(float x) {
    float x2 = x * x;
    float p = fmaf(x2, fmaf(x2, fmaf(x2, -1.9841270e-4f, 8.3333333e-3f),
                            -1.6666667e-1f), 1.0f);
    return x * p;
}

// asin(x), x in [0, ~0.27]  (Taylor deg 7, rel err < 1e-6)
__device__ __forceinline__ float asin_poly(float x) {
    float x2 = x * x;
    float p = fmaf(x2, fmaf(x2, fmaf(x2, 4.4642857e-2f, 7.5000000e-2f),
                            1.6666667e-1f), 1.0f);
    return x * p;
}

// cos(x), |x| <= pi/2  (Taylor deg 10, abs err < 5e-7)
__device__ __forceinline__ float cos_poly(float x) {
    float x2 = x * x;
    return fmaf(x2, fmaf(x2, fmaf(x2, fmaf(x2, fmaf(x2, -2.7557319e-7f,
                 2.4801587e-5f), -1.3888889e-3f), 4.1666667e-2f), -0.5f), 1.0f);
}

// loss for one box pair = 1 - sph_iou
// area(a,b) = 4*acos(-sin(a/2)sin(b/2)) - 2pi == 4*asin(sin(a/2)sin(b/2))
__device__ __forceinline__ float box_loss(float t1, float p1, float a1, float b1,
                                          float t2, float p2, float a2, float b2) {
    float ha1 = 0.5f * a1, hb1 = 0.5f * b1;
    float ha2 = 0.5f * a2, hb2 = 0.5f * b2;

    float area1 = 4.0f * asin_poly(sin_poly(ha1) * sin_poly(hb1));
    float area2 = 4.0f * asin_poly(sin_poly(ha2) * sin_poly(hb2));

    float c   = cos_poly(0.5f * (p1 + p2));
    float dfx = (t2 - t1) * c;
    float dfy = p2 - p1;

    float iw = fminf(ha1, dfx + ha2) - fmaxf(-ha1, dfx - ha2);
    iw = fmaxf(iw, 0.0f);
    float ih = fminf(hb1, dfy + hb2) - fmaxf(-hb1, dfy - hb2);
    ih = fmaxf(ih, 0.0f);

    float inter = 4.0f * asin_poly(sin_poly(0.5f * iw) * sin_poly(0.5f * ih));
    float uni   = fmaxf(area1 + area2 - inter, 1e-8f);
    return 1.0f - __fdividef(inter, uni);
}

// Fused kernel: grid-stride over jobs (4 boxes = 5 float4 per tensor each),
// block partials to g_partials, last-arriving block does the final reduction
// (double precision) and writes the mean. Single launch, graph-replayable,
// no inter-block waiting (deadlock-free by construction).
__global__ void __launch_bounds__(256)
sph_iou_fused_kernel(const float4* __restrict__ pr4, const float4* __restrict__ tg4,
                     int n, float* __restrict__ out) {
    const int jobs = n >> 2;
    float acc = 0.0f;
    for (int j = blockIdx.x * blockDim.x + threadIdx.x; j < jobs;
         j += gridDim.x * blockDim.x) {
        const float4* P = pr4 + (size_t)5 * j;
        const float4* T = tg4 + (size_t)5 * j;
        float4 p0 = __ldcs(P + 0), p1 = __ldcs(P + 1), p2 = __ldcs(P + 2),
               p3 = __ldcs(P + 3), p4 = __ldcs(P + 4);
        float4 q0 = __ldcs(T + 0), q1 = __ldcs(T + 1), q2 = __ldcs(T + 2),
               q3 = __ldcs(T + 3), q4 = __ldcs(T + 4);

        acc += box_loss(p0.x, p0.y, p0.z, p0.w,  q0.x, q0.y, q0.z, q0.w);
        acc += box_loss(p1.y, p1.z, p1.w, p2.x,  q1.y, q1.z, q1.w, q2.x);
        acc += box_loss(p2.z, p2.w, p3.x, p3.y,  q2.z, q2.w, q3.x, q3.y);
        acc += box_loss(p3.w, p4.x, p4.y, p4.z,  q3.w, q4.x, q4.y, q4.z);
    }

    // ---- block reduction (fp32, fixed order) ----
    #pragma unroll
    for (int o = 16; o > 0; o >>= 1)
        acc += __shfl_down_sync(0xFFFFFFFFu, acc, o);

    __shared__ float smf[8];
    int lane = threadIdx.x & 31;
    int wid  = threadIdx.x >> 5;
    if (lane == 0) smf[wid] = acc;
    __syncthreads();

    __shared__ bool isLast;
    if (threadIdx.x == 0) {
        float bsum = 0.0f;
        #pragma unroll
        for (int w = 0; w < 8; ++w) bsum += smf[w];
        g_partials[blockIdx.x] = bsum;
        __threadfence();
        unsigned int t = atomicInc(&g_done, gridDim.x - 1);  // wraps to 0 on last
        isLast = (t == gridDim.x - 1);
    }
    __syncthreads();

    // ---- last block: final reduction in double ----
    if (isLast) {
        __threadfence();  // partials written before the winning atomic are visible
        double s = 0.0;
        for (int i = threadIdx.x; i < (int)gridDim.x; i += blockDim.x)
            s += (double)g_partials[i];

        if (threadIdx.x == 0) {
            int tail = n & 3;
            int base = n - tail;
            const float* prf = (const float*)pr4;
            const float* tgf = (const float*)tg4;
            for (int k = 0; k < tail; ++k) {
                const float* P = prf + (size_t)(base + k) * 5;
                const float* T = tgf + (size_t)(base + k) * 5;
                s += (double)box_loss(P[0], P[1], P[2], P[3],
                                      T[0], T[1], T[2], T[3]);
            }
        }

        __shared__ double smd[256];
        smd[threadIdx.x] = s;
        __syncthreads();
        for (int stride = 128; stride > 0; stride >>= 1) {
            if (threadIdx.x < stride) smd[threadIdx.x] += smd[threadIdx.x + stride];
            __syncthreads();
        }
        if (threadIdx.x == 0) out[0] = (float)(smd[0] / (double)n);
    }
}

extern "C" void kernel_launch(void* const* d_in, const int* in_sizes, int n_in,
                              void* d_out, int out_size) {
    const float* preds   = (const float*)d_in[0];
    const float* targets = (const float*)d_in[1];
    float* out = (float*)d_out;

    int n    = in_sizes[0] / 5;   // number of boxes
    int jobs = n >> 2;            // 4 boxes per thread-job

    int threads = 256;
    // Persistent-style grid: ~8 blocks per SM (148 SMs), grid-stride covers rest.
    int blocks = 1184;
    int needed = (jobs + threads - 1) / threads;
    if (blocks > needed) blocks = needed;
    if (blocks > MAX_BLOCKS) blocks = MAX_BLOCKS;
    if (blocks < 1) blocks = 1;

    sph_iou_fused_kernel<<<blocks, threads>>>(
        (const float4*)preds, (const float4*)targets, n, out);
}

// round 5
// speedup vs baseline: 1.1500x; 1.0781x over previous
#include <cuda_runtime.h>
#include <cuda_bf16.h>

#define MAX_BLOCKS 2048
__device__ float g_partials[MAX_BLOCKS];
__device__ unsigned int g_done = 0;   // self-resets via atomicInc wraparound

// ---- polynomial helpers (restricted domains, fp32, FMA pipe only) ----

// sin(x), x in [0, ~0.54]  (Taylor deg 7, abs err < 1e-8)
__device__ __forceinline__ float sin_poly(float x) {
    float x2 = x * x;
    float p = fmaf(x2, fmaf(x2, fmaf(x2, -1.9841270e-4f, 8.3333333e-3f),
                            -1.6666667e-1f), 1.0f);
    return x * p;
}

// asin(x), x in [0, ~0.27]  (Taylor deg 7, rel err < 1e-6)
__device__ __forceinline__ float asin_poly(float x) {
    float x2 = x * x;
    float p = fmaf(x2, fmaf(x2, fmaf(x2, 4.4642857e-2f, 7.5000000e-2f),
                            1.6666667e-1f), 1.0f);
    return x * p;
}

// cos(x), |x| <= pi/2  (Taylor deg 10, abs err < 5e-7)
__device__ __forceinline__ float cos_poly(float x) {
    float x2 = x * x;
    return fmaf(x2, fmaf(x2, fmaf(x2, fmaf(x2, fmaf(x2, -2.7557319e-7f,
                 2.4801587e-5f), -1.3888889e-3f), 4.1666667e-2f), -0.5f), 1.0f);
}

// loss for one box pair = 1 - sph_iou
// area(a,b) = 4*acos(-sin(a/2)sin(b/2)) - 2pi == 4*asin(sin(a/2)sin(b/2))
__device__ __forceinline__ float box_loss(float t1, float p1, float a1, float b1,
                                          float t2, float p2, float a2, float b2) {
    float ha1 = 0.5f * a1, hb1 = 0.5f * b1;
    float ha2 = 0.5f * a2, hb2 = 0.5f * b2;

    float area1 = 4.0f * asin_poly(sin_poly(ha1) * sin_poly(hb1));
    float area2 = 4.0f * asin_poly(sin_poly(ha2) * sin_poly(hb2));

    float c   = cos_poly(0.5f * (p1 + p2));
    float dfx = (t2 - t1) * c;
    float dfy = p2 - p1;

    float iw = fminf(ha1, dfx + ha2) - fmaxf(-ha1, dfx - ha2);
    iw = fmaxf(iw, 0.0f);
    float ih = fminf(hb1, dfy + hb2) - fmaxf(-hb1, dfy - hb2);
    ih = fmaxf(ih, 0.0f);

    float inter = 4.0f * asin_poly(sin_poly(0.5f * iw) * sin_poly(0.5f * ih));
    float uni   = fmaxf(area1 + area2 - inter, 1e-8f);
    return 1.0f - __fdividef(inter, uni);
}

// Fused kernel: grid-stride over jobs (4 boxes = 5 float4 per tensor each),
// block partials to g_partials, last-arriving block does the final reduction
// (double precision) and writes the mean. Single launch, graph-replayable,
// no inter-block waiting (deadlock-free by construction).
__global__ void __launch_bounds__(256)
sph_iou_fused_kernel(const float4* __restrict__ pr4, const float4* __restrict__ tg4,
                     int n, float* __restrict__ out) {
    const int jobs = n >> 2;
    float acc = 0.0f;
    for (int j = blockIdx.x * blockDim.x + threadIdx.x; j < jobs;
         j += gridDim.x * blockDim.x) {
        const float4* P = pr4 + (size_t)5 * j;
        const float4* T = tg4 + (size_t)5 * j;
        float4 p0 = __ldcs(P + 0), p1 = __ldcs(P + 1), p2 = __ldcs(P + 2),
               p3 = __ldcs(P + 3), p4 = __ldcs(P + 4);
        float4 q0 = __ldcs(T + 0), q1 = __ldcs(T + 1), q2 = __ldcs(T + 2),
               q3 = __ldcs(T + 3), q4 = __ldcs(T + 4);

        acc += box_loss(p0.x, p0.y, p0.z, p0.w,  q0.x, q0.y, q0.z, q0.w);
        acc += box_loss(p1.y, p1.z, p1.w, p2.x,  q1.y, q1.z, q1.w, q2.x);
        acc += box_loss(p2.z, p2.w, p3.x, p3.y,  q2.z, q2.w, q3.x, q3.y);
        acc += box_loss(p3.w, p4.x, p4.y, p4.z,  q3.w, q4.x, q4.y, q4.z);
    }

    // ---- block reduction (fp32, fixed order) ----
    #pragma unroll
    for (int o = 16; o > 0; o >>= 1)
        acc += __shfl_down_sync(0xFFFFFFFFu, acc, o);

    __shared__ float smf[8];
    int lane = threadIdx.x & 31;
    int wid  = threadIdx.x >> 5;
    if (lane == 0) smf[wid] = acc;
    __syncthreads();

    __shared__ bool isLast;
    if (threadIdx.x == 0) {
        float bsum = 0.0f;
        #pragma unroll
        for (int w = 0; w < 8; ++w) bsum += smf[w];
        g_partials[blockIdx.x] = bsum;
        __threadfence();
        unsigned int t = atomicInc(&g_done, gridDim.x - 1);  // wraps to 0 on last
        isLast = (t == gridDim.x - 1);
    }
    __syncthreads();

    // ---- last block: final reduction in double ----
    if (isLast) {
        __threadfence();  // partials written before the winning atomic are visible
        double s = 0.0;
        for (int i = threadIdx.x; i < (int)gridDim.x; i += blockDim.x)
            s += (double)g_partials[i];

        if (threadIdx.x == 0) {
            int tail = n & 3;
            int base = n - tail;
            const float* prf = (const float*)pr4;
            const float* tgf = (const float*)tg4;
            for (int k = 0; k < tail; ++k) {
                const float* P = prf + (size_t)(base + k) * 5;
                const float* T = tgf + (size_t)(base + k) * 5;
                s += (double)box_loss(P[0], P[1], P[2], P[3],
                                      T[0], T[1], T[2], T[3]);
            }
        }

        __shared__ double smd[256];
        smd[threadIdx.x] = s;
        __syncthreads();
        for (int stride = 128; stride > 0; stride >>= 1) {
            if (threadIdx.x < stride) smd[threadIdx.x] += smd[threadIdx.x + stride];
            __syncthreads();
        }
        if (threadIdx.x == 0) out[0] = (float)(smd[0] / (double)n);
    }
}

extern "C" void kernel_launch(void* const* d_in, const int* in_sizes, int n_in,
                              void* d_out, int out_size) {
    const float* preds   = (const float*)d_in[0];
    const float* targets = (const float*)d_in[1];
    float* out = (float*)d_out;

    int n    = in_sizes[0] / 5;   // number of boxes
    int jobs = n >> 2;            // 4 boxes per thread-job

    int threads = 256;
    // Persistent-style grid: ~8 blocks per SM (148 SMs), grid-stride covers rest.
    int blocks = 1184;
    int needed = (jobs + threads - 1) / threads;
    if (blocks > needed) blocks = needed;
    if (blocks > MAX_BLOCKS) blocks = MAX_BLOCKS;
    if (blocks < 1) blocks = 1;

    sph_iou_fused_kernel<<<blocks, threads>>>(
        (const float4*)preds, (const float4*)targets, n, out);
}